// round 2
// baseline (speedup 1.0000x reference)
#include <cuda_runtime.h>

#define NN 100000
#define EE 1000000
#define FIN 128
#define HID 16
#define HEADS 4
#define CC 16
#define H1DIM 64            // HEADS*HID
#define NB 98               // ceil(NN/1024)

// ---------------- scratch (static device globals; no allocation) -------------
__device__ int   g_idx64;           // 1 if edge_index is int64, 0 if int32
__device__ int   g_deg[NN];
__device__ int   g_rowptr[NN + 1];
__device__ int   g_cursor[NN];
__device__ int   g_bsum[128];
__device__ int   g_boff[128];
__device__ int   g_csr[EE];
__device__ float g_h1[NN * H1DIM];
__device__ float4 g_as1[NN];
__device__ float4 g_ad1[NN];
__device__ float g_hact[NN * H1DIM];
__device__ float g_h2[NN * CC];
__device__ float g_as2[NN];
__device__ float g_ad2[NN];

__device__ __forceinline__ float lrelu(float x) { return x > 0.f ? x : 0.2f * x; }

__device__ __forceinline__ int clampN(int v) {
    return v < 0 ? 0 : (v >= NN ? NN - 1 : v);
}

// Load edge endpoint `pos` (element index into a 2*EE logical array),
// handling both int32 and int64 on-disk layouts.
__device__ __forceinline__ int load_idx(const void* __restrict__ ei, int pos, int is64) {
    if (is64) return clampN((int)((const long long*)ei)[pos]);
    return clampN(((const int*)ei)[pos]);
}

// ---------------- dtype probe ------------------------------------------------
// int64 little-endian values < 2^31 have all high (odd) words == 0.
// int32 random values in [0,1e5) make that essentially impossible.
__global__ void probe_kernel(const int* __restrict__ w) {
    if (threadIdx.x == 0 && blockIdx.x == 0) {
        int ok = 1;
        for (int i = 1; i < 2048; i += 2) ok &= (w[i] == 0);
        g_idx64 = ok;
    }
}

// ---------------- CSR build --------------------------------------------------
__global__ void zero_deg_kernel() {
    int i = blockIdx.x * blockDim.x + threadIdx.x;
    if (i < NN) g_deg[i] = 0;
}

__global__ void hist_kernel(const void* __restrict__ ei) {
    int e = blockIdx.x * blockDim.x + threadIdx.x;
    int is64 = g_idx64;
    if (e < EE) atomicAdd(&g_deg[load_idx(ei, EE + e, is64)], 1);
}

__global__ void scanA_kernel() {
    __shared__ int sh[1024];
    int i = blockIdx.x * 1024 + threadIdx.x;
    int v = (i < NN) ? g_deg[i] : 0;
    sh[threadIdx.x] = v;
    __syncthreads();
    for (int o = 1; o < 1024; o <<= 1) {
        int t = (threadIdx.x >= o) ? sh[threadIdx.x - o] : 0;
        __syncthreads();
        sh[threadIdx.x] += t;
        __syncthreads();
    }
    if (i < NN) g_rowptr[i + 1] = sh[threadIdx.x];
    if (threadIdx.x == 1023) g_bsum[blockIdx.x] = sh[1023];
}

__global__ void scanB_kernel() {
    __shared__ int sh[128];
    int t = threadIdx.x;
    int v = (t < NB) ? g_bsum[t] : 0;
    sh[t] = v;
    __syncthreads();
    for (int o = 1; o < 128; o <<= 1) {
        int u = (t >= o) ? sh[t - o] : 0;
        __syncthreads();
        sh[t] += u;
        __syncthreads();
    }
    if (t < NB) g_boff[t] = (t ? sh[t - 1] : 0);
}

__global__ void scanC_kernel() {
    int i = blockIdx.x * blockDim.x + threadIdx.x;
    if (i == 0) g_rowptr[0] = 0;
    if (i < NN) {
        int r = g_rowptr[i + 1] + g_boff[i >> 10];
        g_rowptr[i + 1] = r;
        g_cursor[i] = r - g_deg[i];   // == rowptr[i]
    }
}

__global__ void scatter_kernel(const void* __restrict__ ei) {
    int e = blockIdx.x * blockDim.x + threadIdx.x;
    int is64 = g_idx64;
    if (e < EE) {
        int s = load_idx(ei, e, is64);
        int d = load_idx(ei, EE + e, is64);
        int pos = atomicAdd(&g_cursor[d], 1);
        g_csr[pos] = s;
    }
}

// ---------------- GEMM (W fully in smem, 4 rows/thread) ----------------------
template <int K, int M>
__device__ __forceinline__ void gemm_body(const float* __restrict__ X,
                                          const float* __restrict__ W,
                                          float* __restrict__ Y) {
    constexpr int CG = M / 4;          // float4 column groups
    constexpr int SLOTS = 256 / CG;    // row slots per block
    constexpr int RPT = 4;             // rows per thread
    __shared__ float4 Wsh[K * CG];
    int tid = threadIdx.x;
    for (int i = tid; i < K * CG; i += 256) Wsh[i] = ((const float4*)W)[i];
    __syncthreads();

    int c = tid % CG;
    int slot = tid / CG;
    int row0 = (blockIdx.x * SLOTS + slot) * RPT;
    if (row0 >= NN) return;

    const float4* Xv = (const float4*)X;
    float4* Yv = (float4*)Y;
    float4 acc[RPT];
#pragma unroll
    for (int r = 0; r < RPT; r++) acc[r] = make_float4(0.f, 0.f, 0.f, 0.f);

#pragma unroll 2
    for (int k4 = 0; k4 < K / 4; k4++) {
        float4 w0 = Wsh[(4 * k4 + 0) * CG + c];
        float4 w1 = Wsh[(4 * k4 + 1) * CG + c];
        float4 w2 = Wsh[(4 * k4 + 2) * CG + c];
        float4 w3 = Wsh[(4 * k4 + 3) * CG + c];
#pragma unroll
        for (int r = 0; r < RPT; r++) {
            float4 xv = Xv[(row0 + r) * (K / 4) + k4];
            acc[r].x += xv.x * w0.x + xv.y * w1.x + xv.z * w2.x + xv.w * w3.x;
            acc[r].y += xv.x * w0.y + xv.y * w1.y + xv.z * w2.y + xv.w * w3.y;
            acc[r].z += xv.x * w0.z + xv.y * w1.z + xv.z * w2.z + xv.w * w3.z;
            acc[r].w += xv.x * w0.w + xv.y * w1.w + xv.z * w2.w + xv.w * w3.w;
        }
    }
#pragma unroll
    for (int r = 0; r < RPT; r++) Yv[(row0 + r) * CG + c] = acc[r];
}

__global__ void __launch_bounds__(256) gemm1_kernel(const float* __restrict__ x,
                                                    const float* __restrict__ W1) {
    gemm_body<FIN, H1DIM>(x, W1, g_h1);
}

__global__ void __launch_bounds__(256) gemm2_kernel(const float* __restrict__ W2) {
    gemm_body<H1DIM, CC>(g_hact, W2, g_h2);
}

// ---------------- attention coefficients -------------------------------------
__global__ void attn1_kernel(const float* __restrict__ asrc, const float* __restrict__ adst) {
    int i = blockIdx.x * blockDim.x + threadIdx.x;
    if (i >= NN) return;
    const float4* hv = (const float4*)g_h1 + i * 16;
    const float4* av = (const float4*)asrc;   // [4][16] -> 16 float4
    const float4* dv = (const float4*)adst;
    float sa[4], sd[4];
#pragma unroll
    for (int h = 0; h < 4; h++) {
        float ta = 0.f, td = 0.f;
#pragma unroll
        for (int j = 0; j < 4; j++) {
            float4 xv = hv[h * 4 + j];
            float4 a = av[h * 4 + j];
            float4 d = dv[h * 4 + j];
            ta += xv.x * a.x + xv.y * a.y + xv.z * a.z + xv.w * a.w;
            td += xv.x * d.x + xv.y * d.y + xv.z * d.z + xv.w * d.w;
        }
        sa[h] = ta; sd[h] = td;
    }
    g_as1[i] = make_float4(sa[0], sa[1], sa[2], sa[3]);
    g_ad1[i] = make_float4(sd[0], sd[1], sd[2], sd[3]);
}

__global__ void attn2_kernel(const float* __restrict__ asrc, const float* __restrict__ adst) {
    int i = blockIdx.x * blockDim.x + threadIdx.x;
    if (i >= NN) return;
    const float4* hv = (const float4*)g_h2 + i * 4;
    const float4* av = (const float4*)asrc;   // [16] -> 4 float4
    const float4* dv = (const float4*)adst;
    float ta = 0.f, td = 0.f;
#pragma unroll
    for (int j = 0; j < 4; j++) {
        float4 xv = hv[j];
        float4 a = av[j];
        float4 d = dv[j];
        ta += xv.x * a.x + xv.y * a.y + xv.z * a.z + xv.w * a.w;
        td += xv.x * d.x + xv.y * d.y + xv.z * d.z + xv.w * d.w;
    }
    g_as2[i] = ta;
    g_ad2[i] = td;
}

// ---------------- layer-1 gather softmax + aggregation (warp per dst) --------
__global__ void __launch_bounds__(256) gat_agg1_kernel(const float* __restrict__ b1) {
    __shared__ float4 sh_ex[8][32];
    int warp = threadIdx.x >> 5, lane = threadIdx.x & 31;
    int dn = blockIdx.x * 8 + warp;
    if (dn >= NN) return;

    float4 ad4 = g_ad1[dn];
    int row = g_rowptr[dn];
    int deg = g_rowptr[dn + 1] - row;
    float4 den = make_float4(0.f, 0.f, 0.f, 0.f);
    float2 acc = make_float2(0.f, 0.f);
    int myh = lane >> 3;                      // lane holds h1 elems 2l,2l+1
    const float2* h1v2 = (const float2*)g_h1;

    for (int base = 0; base < deg; base += 32) {
        int j = base + lane;
        int s = 0;
        if (j < deg) {
            s = g_csr[row + j];
            float4 as4 = g_as1[s];
            float4 ex4;
            ex4.x = __expf(lrelu(as4.x + ad4.x));
            ex4.y = __expf(lrelu(as4.y + ad4.y));
            ex4.z = __expf(lrelu(as4.z + ad4.z));
            ex4.w = __expf(lrelu(as4.w + ad4.w));
            den.x += ex4.x; den.y += ex4.y; den.z += ex4.z; den.w += ex4.w;
            sh_ex[warp][lane] = ex4;
        }
        __syncwarp();
        int cnt = min(32, deg - base);
        for (int jj = 0; jj < cnt; jj++) {
            int sj = __shfl_sync(0xffffffffu, s, jj);
            float exm = ((const float*)&sh_ex[warp][jj])[myh];
            float2 hv = h1v2[sj * 32 + lane];
            acc.x += exm * hv.x;
            acc.y += exm * hv.y;
        }
        __syncwarp();
    }
#pragma unroll
    for (int o = 16; o; o >>= 1) {
        den.x += __shfl_xor_sync(0xffffffffu, den.x, o);
        den.y += __shfl_xor_sync(0xffffffffu, den.y, o);
        den.z += __shfl_xor_sync(0xffffffffu, den.z, o);
        den.w += __shfl_xor_sync(0xffffffffu, den.w, o);
    }
    // self loop
    float4 asd = g_as1[dn];
    float4 exs;
    exs.x = __expf(lrelu(asd.x + ad4.x));
    exs.y = __expf(lrelu(asd.y + ad4.y));
    exs.z = __expf(lrelu(asd.z + ad4.z));
    exs.w = __expf(lrelu(asd.w + ad4.w));
    den.x += exs.x; den.y += exs.y; den.z += exs.z; den.w += exs.w;
    float exm_self = myh == 0 ? exs.x : myh == 1 ? exs.y : myh == 2 ? exs.z : exs.w;
    float2 hd = h1v2[dn * 32 + lane];
    acc.x += exm_self * hd.x;
    acc.y += exm_self * hd.y;

    float dm = (myh == 0 ? den.x : myh == 1 ? den.y : myh == 2 ? den.z : den.w) + 1e-16f;
    float inv = 1.f / dm;
    float ox = acc.x * inv + b1[2 * lane];
    float oy = acc.y * inv + b1[2 * lane + 1];
    ox = ox > 0.f ? ox : expm1f(ox);          // elu
    oy = oy > 0.f ? oy : expm1f(oy);
    ((float2*)g_hact)[dn * 32 + lane] = make_float2(ox, oy);
}

// ---------------- layer-2 gather softmax + aggregation (warp per dst) --------
__global__ void __launch_bounds__(256) gat_agg2_kernel(const float* __restrict__ b2,
                                                       float* __restrict__ out) {
    int warp = threadIdx.x >> 5, lane = threadIdx.x & 31;
    int dn = blockIdx.x * 8 + warp;
    if (dn >= NN) return;

    float ad = g_ad2[dn];
    int row = g_rowptr[dn];
    int deg = g_rowptr[dn + 1] - row;
    float den = 0.f;
    float acc = 0.f;

    for (int base = 0; base < deg; base += 32) {
        int j = base + lane;
        int s = 0;
        float ex = 0.f;
        if (j < deg) {
            s = g_csr[row + j];
            ex = __expf(lrelu(g_as2[s] + ad));
            den += ex;
        }
        int cnt = min(32, deg - base);
        for (int jj = 0; jj < cnt; jj++) {
            int sj = __shfl_sync(0xffffffffu, s, jj);
            float exm = __shfl_sync(0xffffffffu, ex, jj);
            if (lane < CC) acc += exm * g_h2[sj * CC + lane];
        }
    }
#pragma unroll
    for (int o = 16; o; o >>= 1) den += __shfl_xor_sync(0xffffffffu, den, o);

    float exs = __expf(lrelu(g_as2[dn] + ad));
    den += exs;
    if (lane < CC) {
        acc += exs * g_h2[dn * CC + lane];
        out[dn * CC + lane] = acc / (den + 1e-16f) + b2[lane];
    }
}

// ---------------- launch ------------------------------------------------------
extern "C" void kernel_launch(void* const* d_in, const int* in_sizes, int n_in,
                              void* d_out, int out_size) {
    const float* x      = (const float*)d_in[0];
    const void*  ei     = d_in[1];                 // int32 or int64, probed on device
    const float* W1     = (const float*)d_in[2];
    const float* a_src1 = (const float*)d_in[3];
    const float* a_dst1 = (const float*)d_in[4];
    const float* b1     = (const float*)d_in[5];
    const float* W2     = (const float*)d_in[6];
    const float* a_src2 = (const float*)d_in[7];
    const float* a_dst2 = (const float*)d_in[8];
    const float* b2     = (const float*)d_in[9];
    float* out = (float*)d_out;

    (void)in_sizes; (void)n_in; (void)out_size;

    const int nThreads = 256;
    const int nBlocksN = (NN + nThreads - 1) / nThreads;
    const int nBlocksE = (EE + nThreads - 1) / nThreads;

    // dtype probe + CSR by destination
    probe_kernel<<<1, 32>>>((const int*)ei);
    zero_deg_kernel<<<nBlocksN, nThreads>>>();
    hist_kernel<<<nBlocksE, nThreads>>>(ei);
    scanA_kernel<<<NB, 1024>>>();
    scanB_kernel<<<1, 128>>>();
    scanC_kernel<<<nBlocksN, nThreads>>>();
    scatter_kernel<<<nBlocksE, nThreads>>>(ei);

    // layer 1
    gemm1_kernel<<<(NN + 63) / 64, 256>>>(x, W1);
    attn1_kernel<<<nBlocksN, nThreads>>>(a_src1, a_dst1);
    gat_agg1_kernel<<<(NN + 7) / 8, 256>>>(b1);

    // layer 2
    gemm2_kernel<<<(NN + 255) / 256, 256>>>(W2);
    attn2_kernel<<<nBlocksN, nThreads>>>(a_src2, a_dst2);
    gat_agg2_kernel<<<(NN + 7) / 8, 256>>>(b2, out);
}

// round 3
// speedup vs baseline: 1.1667x; 1.1667x over previous
#include <cuda_runtime.h>

#define NN 100000
#define EE 1000000
#define FIN 128
#define HID 16
#define HEADS 4
#define CC 16
#define H1DIM 64            // HEADS*HID
#define NB 98               // ceil(NN/1024)

// ---------------- scratch (static device globals; no allocation) -------------
__device__ int   g_idx64;           // 1 if edge_index is int64, 0 if int32
__device__ int   g_deg[NN];
__device__ int   g_rowptr[NN + 1];
__device__ int   g_cursor[NN];
__device__ int   g_bsum[128];
__device__ int   g_boff[128];
__device__ int   g_csr[EE];
__device__ __align__(16) float g_h1[NN * H1DIM];
__device__ __align__(16) float g_as1[NN * 4];
__device__ __align__(16) float g_ad1[NN * 4];
__device__ __align__(16) float g_hact[NN * H1DIM];
__device__ __align__(16) float g_h2[NN * CC];
__device__ float g_as2[NN];
__device__ float g_ad2[NN];

__device__ __forceinline__ float lrelu(float x) { return x > 0.f ? x : 0.2f * x; }

__device__ __forceinline__ int clampN(int v) {
    return v < 0 ? 0 : (v >= NN ? NN - 1 : v);
}

__device__ __forceinline__ int load_idx(const void* __restrict__ ei, int pos, int is64) {
    if (is64) return clampN((int)((const long long*)ei)[pos]);
    return clampN(((const int*)ei)[pos]);
}

__device__ __forceinline__ float sel4(float4 v, int k) {
    return k == 0 ? v.x : k == 1 ? v.y : k == 2 ? v.z : v.w;
}

// ---------------- dtype probe (warp-parallel) --------------------------------
__global__ void probe_kernel(const int* __restrict__ w) {
    int ok = 1;
    for (int k = threadIdx.x; k < 1024; k += 32) ok &= (w[2 * k + 1] == 0);
    ok = __all_sync(0xffffffffu, ok != 0);
    if (threadIdx.x == 0) g_idx64 = ok;
}

// ---------------- CSR build --------------------------------------------------
__global__ void zero_deg_kernel() {
    int i = blockIdx.x * blockDim.x + threadIdx.x;
    if (i < NN) g_deg[i] = 0;
}

__global__ void hist_kernel(const void* __restrict__ ei) {
    int e = blockIdx.x * blockDim.x + threadIdx.x;
    int is64 = g_idx64;
    if (e < EE) atomicAdd(&g_deg[load_idx(ei, EE + e, is64)], 1);
}

__global__ void scanA_kernel() {
    __shared__ int sh[1024];
    int i = blockIdx.x * 1024 + threadIdx.x;
    int v = (i < NN) ? g_deg[i] : 0;
    sh[threadIdx.x] = v;
    __syncthreads();
    for (int o = 1; o < 1024; o <<= 1) {
        int t = (threadIdx.x >= o) ? sh[threadIdx.x - o] : 0;
        __syncthreads();
        sh[threadIdx.x] += t;
        __syncthreads();
    }
    if (i < NN) g_rowptr[i + 1] = sh[threadIdx.x];
    if (threadIdx.x == 1023) g_bsum[blockIdx.x] = sh[1023];
}

__global__ void scanB_kernel() {
    __shared__ int sh[128];
    int t = threadIdx.x;
    int v = (t < NB) ? g_bsum[t] : 0;
    sh[t] = v;
    __syncthreads();
    for (int o = 1; o < 128; o <<= 1) {
        int u = (t >= o) ? sh[t - o] : 0;
        __syncthreads();
        sh[t] += u;
        __syncthreads();
    }
    if (t < NB) g_boff[t] = (t ? sh[t - 1] : 0);
}

__global__ void scanC_kernel() {
    int i = blockIdx.x * blockDim.x + threadIdx.x;
    if (i == 0) g_rowptr[0] = 0;
    if (i < NN) {
        int r = g_rowptr[i + 1] + g_boff[i >> 10];
        g_rowptr[i + 1] = r;
        g_cursor[i] = r - g_deg[i];
    }
}

__global__ void scatter_kernel(const void* __restrict__ ei) {
    int e = blockIdx.x * blockDim.x + threadIdx.x;
    int is64 = g_idx64;
    if (e < EE) {
        int s = load_idx(ei, e, is64);
        int d = load_idx(ei, EE + e, is64);
        int pos = atomicAdd(&g_cursor[d], 1);
        g_csr[pos] = s;
    }
}

// ---------------- GEMM core (W fully in smem, 4 rows/thread) -----------------
// No early returns: all 256 threads stay live for epilogue shuffles.
template <int K, int M>
__device__ __forceinline__ void gemm_core(const float* __restrict__ X,
                                          const float* __restrict__ W,
                                          float* __restrict__ Y,
                                          float4 acc[4], int& row0_out, int& c_out) {
    constexpr int CG = M / 4;          // float4 column groups
    constexpr int SLOTS = 256 / CG;    // row slots per block
    __shared__ float4 Wsh[K * CG];
    int tid = threadIdx.x;
    for (int i = tid; i < K * CG; i += 256) Wsh[i] = ((const float4*)W)[i];
    __syncthreads();

    int c = tid % CG;
    int slot = tid / CG;
    int row0 = (blockIdx.x * SLOTS + slot) * 4;
    int rowL = (row0 < NN) ? row0 : 0;     // clamp for safe loads
    row0_out = row0;
    c_out = c;

    const float4* Xv = (const float4*)X;
#pragma unroll
    for (int r = 0; r < 4; r++) acc[r] = make_float4(0.f, 0.f, 0.f, 0.f);

#pragma unroll 2
    for (int k4 = 0; k4 < K / 4; k4++) {
        float4 w0 = Wsh[(4 * k4 + 0) * CG + c];
        float4 w1 = Wsh[(4 * k4 + 1) * CG + c];
        float4 w2 = Wsh[(4 * k4 + 2) * CG + c];
        float4 w3 = Wsh[(4 * k4 + 3) * CG + c];
#pragma unroll
        for (int r = 0; r < 4; r++) {
            float4 xv = Xv[(rowL + r) * (K / 4) + k4];
            acc[r].x += xv.x * w0.x + xv.y * w1.x + xv.z * w2.x + xv.w * w3.x;
            acc[r].y += xv.x * w0.y + xv.y * w1.y + xv.z * w2.y + xv.w * w3.y;
            acc[r].z += xv.x * w0.z + xv.y * w1.z + xv.z * w2.z + xv.w * w3.z;
            acc[r].w += xv.x * w0.w + xv.y * w1.w + xv.z * w2.w + xv.w * w3.w;
        }
    }
    if (row0 < NN) {
        float4* Yv = (float4*)Y;
#pragma unroll
        for (int r = 0; r < 4; r++) Yv[(row0 + r) * CG + c] = acc[r];
    }
}

// gemm1 + fused attn1: as1/ad1 per head via width-4 shfl reduce over the 16
// column-group lanes (4 lanes per head).
__global__ void __launch_bounds__(256) gemm1_kernel(const float* __restrict__ x,
                                                    const float* __restrict__ W1,
                                                    const float* __restrict__ asrc,
                                                    const float* __restrict__ adst) {
    float4 acc[4];
    int row0, c;
    gemm_core<FIN, H1DIM>(x, W1, g_h1, acc, row0, c);

    float4 a1 = ((const float4*)asrc)[c];
    float4 d1 = ((const float4*)adst)[c];
    int head = c >> 2;
#pragma unroll
    for (int r = 0; r < 4; r++) {
        float ta = acc[r].x * a1.x + acc[r].y * a1.y + acc[r].z * a1.z + acc[r].w * a1.w;
        float td = acc[r].x * d1.x + acc[r].y * d1.y + acc[r].z * d1.z + acc[r].w * d1.w;
        ta += __shfl_xor_sync(0xffffffffu, ta, 1, 4);
        ta += __shfl_xor_sync(0xffffffffu, ta, 2, 4);
        td += __shfl_xor_sync(0xffffffffu, td, 1, 4);
        td += __shfl_xor_sync(0xffffffffu, td, 2, 4);
        if ((c & 3) == 0 && row0 < NN) {
            g_as1[(row0 + r) * 4 + head] = ta;
            g_ad1[(row0 + r) * 4 + head] = td;
        }
    }
}

// gemm2 + fused attn2: single head, width-4 reduce over the 4 column lanes.
__global__ void __launch_bounds__(256) gemm2_kernel(const float* __restrict__ W2,
                                                    const float* __restrict__ asrc,
                                                    const float* __restrict__ adst) {
    float4 acc[4];
    int row0, c;
    gemm_core<H1DIM, CC>(g_hact, W2, g_h2, acc, row0, c);

    float4 a2 = ((const float4*)asrc)[c];
    float4 d2 = ((const float4*)adst)[c];
#pragma unroll
    for (int r = 0; r < 4; r++) {
        float ta = acc[r].x * a2.x + acc[r].y * a2.y + acc[r].z * a2.z + acc[r].w * a2.w;
        float td = acc[r].x * d2.x + acc[r].y * d2.y + acc[r].z * d2.z + acc[r].w * d2.w;
        ta += __shfl_xor_sync(0xffffffffu, ta, 1, 4);
        ta += __shfl_xor_sync(0xffffffffu, ta, 2, 4);
        td += __shfl_xor_sync(0xffffffffu, td, 1, 4);
        td += __shfl_xor_sync(0xffffffffu, td, 2, 4);
        if ((c & 3) == 0 && row0 < NN) {
            g_as2[row0 + r] = ta;
            g_ad2[row0 + r] = td;
        }
    }
}

// ---------------- layer-1 softmax + aggregation ------------------------------
// Warp per dst. Half-warps each fetch a different edge's h1 row as float4
// (2 edges per inner iteration, LDG.128), edge metadata via smem.
__global__ void __launch_bounds__(256) gat_agg1_kernel(const float* __restrict__ b1) {
    __shared__ float4 sh_ex[8][32];
    __shared__ int    sh_s[8][32];
    int warp = threadIdx.x >> 5, lane = threadIdx.x & 31;
    int half = lane >> 4, hl = lane & 15;
    int head16 = hl >> 2;                  // head owning float4 group hl
    int dn = blockIdx.x * 8 + warp;        // grid covers NN exactly

    const float4* as1v = (const float4*)g_as1;
    const float4* ad1v = (const float4*)g_ad1;
    const float4* h1v4 = (const float4*)g_h1;

    float4 ad4 = ad1v[dn];
    int row = g_rowptr[dn];
    int deg = g_rowptr[dn + 1] - row;
    float4 den = make_float4(0.f, 0.f, 0.f, 0.f);
    float4 acc = make_float4(0.f, 0.f, 0.f, 0.f);

    for (int base = 0; base < deg; base += 32) {
        int j = base + lane;
        bool valid = j < deg;
        int s = g_csr[row + (valid ? j : deg - 1)];
        float4 as4 = as1v[s];
        float4 ex4;
        ex4.x = __expf(lrelu(as4.x + ad4.x));
        ex4.y = __expf(lrelu(as4.y + ad4.y));
        ex4.z = __expf(lrelu(as4.z + ad4.z));
        ex4.w = __expf(lrelu(as4.w + ad4.w));
        if (valid) {
            den.x += ex4.x; den.y += ex4.y; den.z += ex4.z; den.w += ex4.w;
        }
        sh_s[warp][lane] = s;
        sh_ex[warp][lane] = ex4;
        __syncwarp();

        int cnt = min(32, deg - base);
        int jj = 0;
        for (; jj + 4 <= cnt; jj += 4) {       // 2 pair-steps => MLP 2 per lane
            int e0 = jj + half, e1 = jj + 2 + half;
            int s0 = sh_s[warp][e0];
            int s1 = sh_s[warp][e1];
            float x0 = ((const float*)&sh_ex[warp][e0])[head16];
            float x1 = ((const float*)&sh_ex[warp][e1])[head16];
            float4 h0 = h1v4[s0 * 16 + hl];
            float4 h1r = h1v4[s1 * 16 + hl];
            acc.x += x0 * h0.x; acc.y += x0 * h0.y; acc.z += x0 * h0.z; acc.w += x0 * h0.w;
            acc.x += x1 * h1r.x; acc.y += x1 * h1r.y; acc.z += x1 * h1r.z; acc.w += x1 * h1r.w;
        }
        for (; jj < cnt; jj += 2) {
            int e = jj + half;
            if (e < cnt) {
                int s0 = sh_s[warp][e];
                float x0 = ((const float*)&sh_ex[warp][e])[head16];
                float4 h0 = h1v4[s0 * 16 + hl];
                acc.x += x0 * h0.x; acc.y += x0 * h0.y; acc.z += x0 * h0.z; acc.w += x0 * h0.w;
            }
        }
        __syncwarp();
    }

    // denominator: full-warp reduce (all heads)
#pragma unroll
    for (int o = 16; o; o >>= 1) {
        den.x += __shfl_xor_sync(0xffffffffu, den.x, o);
        den.y += __shfl_xor_sync(0xffffffffu, den.y, o);
        den.z += __shfl_xor_sync(0xffffffffu, den.z, o);
        den.w += __shfl_xor_sync(0xffffffffu, den.w, o);
    }
    // combine half-warp accumulators
    acc.x += __shfl_xor_sync(0xffffffffu, acc.x, 16);
    acc.y += __shfl_xor_sync(0xffffffffu, acc.y, 16);
    acc.z += __shfl_xor_sync(0xffffffffu, acc.z, 16);
    acc.w += __shfl_xor_sync(0xffffffffu, acc.w, 16);

    // self loop + output (half 0 writes)
    float4 asd = as1v[dn];
    float4 exs;
    exs.x = __expf(lrelu(asd.x + ad4.x));
    exs.y = __expf(lrelu(asd.y + ad4.y));
    exs.z = __expf(lrelu(asd.z + ad4.z));
    exs.w = __expf(lrelu(asd.w + ad4.w));
    den.x += exs.x; den.y += exs.y; den.z += exs.z; den.w += exs.w;

    if (half == 0) {
        float exm_self = sel4(exs, head16);
        float4 hd = h1v4[dn * 16 + hl];
        acc.x += exm_self * hd.x; acc.y += exm_self * hd.y;
        acc.z += exm_self * hd.z; acc.w += exm_self * hd.w;
        float inv = 1.f / (sel4(den, head16) + 1e-16f);
        float4 bv = ((const float4*)b1)[hl];
        float4 o;
        o.x = acc.x * inv + bv.x;
        o.y = acc.y * inv + bv.y;
        o.z = acc.z * inv + bv.z;
        o.w = acc.w * inv + bv.w;
        o.x = o.x > 0.f ? o.x : expm1f(o.x);
        o.y = o.y > 0.f ? o.y : expm1f(o.y);
        o.z = o.z > 0.f ? o.z : expm1f(o.z);
        o.w = o.w > 0.f ? o.w : expm1f(o.w);
        ((float4*)g_hact)[dn * 16 + hl] = o;
    }
}

// ---------------- layer-2 softmax + aggregation ------------------------------
// Half-warp (16 lanes) per dst node; 2 dsts per warp; CC=16 features per lane.
__global__ void __launch_bounds__(256) gat_agg2_kernel(const float* __restrict__ b2,
                                                       float* __restrict__ out) {
    __shared__ int   sh_s[8][32];
    __shared__ float sh_ex[8][32];
    int warp = threadIdx.x >> 5, lane = threadIdx.x & 31;
    int half = lane >> 4, hl = lane & 15;
    int dn = (blockIdx.x * 8 + warp) * 2 + half;   // grid covers NN exactly

    float ad = g_ad2[dn];
    int row = g_rowptr[dn];
    int deg = g_rowptr[dn + 1] - row;
    int degmax = max(deg, __shfl_xor_sync(0xffffffffu, deg, 16));
    float den = 0.f;
    float a0 = 0.f, a1 = 0.f;

    for (int base = 0; base < degmax; base += 16) {
        int j = base + hl;
        bool valid = j < deg;
        int s = g_csr[valid ? row + j : 0];
        float ex = 0.f;
        if (valid) {
            ex = __expf(lrelu(g_as2[s] + ad));
            den += ex;
        }
        sh_s[warp][half * 16 + hl] = s;
        sh_ex[warp][half * 16 + hl] = ex;
        __syncwarp();

        int cnt = deg - base;
        cnt = cnt < 0 ? 0 : (cnt > 16 ? 16 : cnt);
        int bs = half * 16;
        int jj = 0;
        for (; jj + 2 <= cnt; jj += 2) {
            int s0 = sh_s[warp][bs + jj];
            int s1 = sh_s[warp][bs + jj + 1];
            float x0 = sh_ex[warp][bs + jj];
            float x1 = sh_ex[warp][bs + jj + 1];
            a0 += x0 * g_h2[s0 * 16 + hl];
            a1 += x1 * g_h2[s1 * 16 + hl];
        }
        if (jj < cnt) {
            int s0 = sh_s[warp][bs + jj];
            float x0 = sh_ex[warp][bs + jj];
            a0 += x0 * g_h2[s0 * 16 + hl];
        }
        __syncwarp();
    }
    float acc = a0 + a1;
#pragma unroll
    for (int o = 8; o; o >>= 1) den += __shfl_xor_sync(0xffffffffu, den, o, 16);

    float exs = __expf(lrelu(g_as2[dn] + ad));
    den += exs;
    acc += exs * g_h2[dn * 16 + hl];
    out[dn * 16 + hl] = acc / (den + 1e-16f) + b2[hl];
}

// ---------------- launch ------------------------------------------------------
extern "C" void kernel_launch(void* const* d_in, const int* in_sizes, int n_in,
                              void* d_out, int out_size) {
    const float* x      = (const float*)d_in[0];
    const void*  ei     = d_in[1];
    const float* W1     = (const float*)d_in[2];
    const float* a_src1 = (const float*)d_in[3];
    const float* a_dst1 = (const float*)d_in[4];
    const float* b1     = (const float*)d_in[5];
    const float* W2     = (const float*)d_in[6];
    const float* a_src2 = (const float*)d_in[7];
    const float* a_dst2 = (const float*)d_in[8];
    const float* b2     = (const float*)d_in[9];
    float* out = (float*)d_out;

    (void)in_sizes; (void)n_in; (void)out_size;

    const int nThreads = 256;
    const int nBlocksN = (NN + nThreads - 1) / nThreads;
    const int nBlocksE = (EE + nThreads - 1) / nThreads;

    probe_kernel<<<1, 32>>>((const int*)ei);
    zero_deg_kernel<<<nBlocksN, nThreads>>>();
    hist_kernel<<<nBlocksE, nThreads>>>(ei);
    scanA_kernel<<<NB, 1024>>>();
    scanB_kernel<<<1, 128>>>();
    scanC_kernel<<<nBlocksN, nThreads>>>();
    scatter_kernel<<<nBlocksE, nThreads>>>(ei);

    gemm1_kernel<<<(NN + 63) / 64, 256>>>(x, W1, a_src1, a_dst1);
    gat_agg1_kernel<<<(NN + 7) / 8, 256>>>(b1);

    gemm2_kernel<<<(NN + 255) / 256, 256>>>(W2, a_src2, a_dst2);
    gat_agg2_kernel<<<(NN + 15) / 16, 256>>>(b2, out);
}

// round 4
// speedup vs baseline: 1.4220x; 1.2188x over previous
#include <cuda_runtime.h>

#define NN 100000
#define EE 1000000
#define FIN 128
#define HID 16
#define HEADS 4
#define CC 16
#define H1DIM 64            // HEADS*HID
#define NB2 25              // ceil(NN/4096) scan blocks

// ---------------- scratch (static device globals; no allocation) -------------
__device__ int   g_idx64;           // 1 if edge_index is int64, 0 if int32
__device__ __align__(16) int g_deg[NN];
__device__ int   g_rowptr[NN + 1];
__device__ int   g_cursor[NN];
__device__ int   g_bsum[32];
__device__ int   g_boff[32];
__device__ int   g_csr[EE];
__device__ __align__(16) float g_h1[NN * H1DIM];
__device__ __align__(16) float g_as1[NN * 4];
__device__ __align__(16) float g_ad1[NN * 4];
__device__ __align__(16) float g_hact[NN * H1DIM];
__device__ __align__(16) float g_h2[NN * CC];
__device__ float g_as2[NN];
__device__ float g_ad2[NN];

__device__ __forceinline__ float lrelu(float x) { return x > 0.f ? x : 0.2f * x; }

__device__ __forceinline__ int clampN(int v) {
    return v < 0 ? 0 : (v >= NN ? NN - 1 : v);
}

__device__ __forceinline__ int load_idx(const void* __restrict__ ei, int pos, int is64) {
    if (is64) return clampN((int)((const long long*)ei)[pos]);
    return clampN(((const int*)ei)[pos]);
}

__device__ __forceinline__ float sel4(float4 v, int k) {
    return k == 0 ? v.x : k == 1 ? v.y : k == 2 ? v.z : v.w;
}

// ---------------- dtype probe (warp-parallel) --------------------------------
__global__ void probe_kernel(const int* __restrict__ w) {
    int ok = 1;
    for (int k = threadIdx.x; k < 1024; k += 32) ok &= (w[2 * k + 1] == 0);
    ok = __all_sync(0xffffffffu, ok != 0);
    if (threadIdx.x == 0) g_idx64 = ok;
}

// ---------------- CSR build --------------------------------------------------
__global__ void zero_deg_kernel() {
    int i = blockIdx.x * blockDim.x + threadIdx.x;
    if (i < NN) g_deg[i] = 0;
}

__global__ void hist_kernel(const void* __restrict__ ei) {
    int e = blockIdx.x * blockDim.x + threadIdx.x;
    int is64 = g_idx64;
    if (e < EE) atomicAdd(&g_deg[load_idx(ei, EE + e, is64)], 1);
}

// shfl-based scan: 4 elements/thread, 4096/block, 25 blocks.
__global__ void __launch_bounds__(1024) scanA_kernel() {
    __shared__ int warp_sums[32];
    int t = threadIdx.x;
    int base = blockIdx.x * 4096 + t * 4;
    int4 v = make_int4(0, 0, 0, 0);
    if (base + 3 < NN) {
        v = *(const int4*)&g_deg[base];
    } else {
        if (base + 0 < NN) v.x = g_deg[base + 0];
        if (base + 1 < NN) v.y = g_deg[base + 1];
        if (base + 2 < NN) v.z = g_deg[base + 2];
        if (base + 3 < NN) v.w = g_deg[base + 3];
    }
    int s1 = v.x, s2 = s1 + v.y, s3 = s2 + v.z, s4 = s3 + v.w;
    int lane = t & 31, wid = t >> 5;
    int ws = s4;
#pragma unroll
    for (int o = 1; o < 32; o <<= 1) {
        int u = __shfl_up_sync(0xffffffffu, ws, o);
        if (lane >= o) ws += u;
    }
    if (lane == 31) warp_sums[wid] = ws;
    __syncthreads();
    if (wid == 0) {
        int x = warp_sums[lane];
#pragma unroll
        for (int o = 1; o < 32; o <<= 1) {
            int u = __shfl_up_sync(0xffffffffu, x, o);
            if (lane >= o) x += u;
        }
        warp_sums[lane] = x;
    }
    __syncthreads();
    int excl = (wid ? warp_sums[wid - 1] : 0) + ws - s4;
    if (base + 0 < NN) g_rowptr[base + 1] = excl + s1;
    if (base + 1 < NN) g_rowptr[base + 2] = excl + s2;
    if (base + 2 < NN) g_rowptr[base + 3] = excl + s3;
    if (base + 3 < NN) g_rowptr[base + 4] = excl + s4;
    if (t == 0) g_bsum[blockIdx.x] = warp_sums[31];
}

__global__ void scanB_kernel() {
    int lane = threadIdx.x;
    int v = (lane < NB2) ? g_bsum[lane] : 0;
    int x = v;
#pragma unroll
    for (int o = 1; o < 32; o <<= 1) {
        int u = __shfl_up_sync(0xffffffffu, x, o);
        if (lane >= o) x += u;
    }
    if (lane < NB2) g_boff[lane] = x - v;   // exclusive
}

__global__ void scanC_kernel() {
    int i = blockIdx.x * blockDim.x + threadIdx.x;
    if (i == 0) g_rowptr[0] = 0;
    if (i < NN) {
        int r = g_rowptr[i + 1] + g_boff[i >> 12];
        g_rowptr[i + 1] = r;
        g_cursor[i] = r - g_deg[i];
    }
}

__global__ void scatter_kernel(const void* __restrict__ ei) {
    int e = blockIdx.x * blockDim.x + threadIdx.x;
    int is64 = g_idx64;
    if (e < EE) {
        int s = load_idx(ei, e, is64);
        int d = load_idx(ei, EE + e, is64);
        int pos = atomicAdd(&g_cursor[d], 1);
        g_csr[pos] = s;
    }
}

// ---------------- GEMM core (W fully in smem, 4 rows/thread) -----------------
template <int K, int M>
__device__ __forceinline__ void gemm_core(const float* __restrict__ X,
                                          const float* __restrict__ W,
                                          float* __restrict__ Y,
                                          float4 acc[4], int& row0_out, int& c_out) {
    constexpr int CG = M / 4;
    constexpr int SLOTS = 256 / CG;
    __shared__ float4 Wsh[K * CG];
    int tid = threadIdx.x;
    for (int i = tid; i < K * CG; i += 256) Wsh[i] = ((const float4*)W)[i];
    __syncthreads();

    int c = tid % CG;
    int slot = tid / CG;
    int row0 = (blockIdx.x * SLOTS + slot) * 4;
    int rowL = (row0 < NN) ? row0 : 0;
    row0_out = row0;
    c_out = c;

    const float4* Xv = (const float4*)X;
#pragma unroll
    for (int r = 0; r < 4; r++) acc[r] = make_float4(0.f, 0.f, 0.f, 0.f);

#pragma unroll 2
    for (int k4 = 0; k4 < K / 4; k4++) {
        float4 w0 = Wsh[(4 * k4 + 0) * CG + c];
        float4 w1 = Wsh[(4 * k4 + 1) * CG + c];
        float4 w2 = Wsh[(4 * k4 + 2) * CG + c];
        float4 w3 = Wsh[(4 * k4 + 3) * CG + c];
#pragma unroll
        for (int r = 0; r < 4; r++) {
            float4 xv = Xv[(rowL + r) * (K / 4) + k4];
            acc[r].x += xv.x * w0.x + xv.y * w1.x + xv.z * w2.x + xv.w * w3.x;
            acc[r].y += xv.x * w0.y + xv.y * w1.y + xv.z * w2.y + xv.w * w3.y;
            acc[r].z += xv.x * w0.z + xv.y * w1.z + xv.z * w2.z + xv.w * w3.z;
            acc[r].w += xv.x * w0.w + xv.y * w1.w + xv.z * w2.w + xv.w * w3.w;
        }
    }
    if (row0 < NN) {
        float4* Yv = (float4*)Y;
#pragma unroll
        for (int r = 0; r < 4; r++) Yv[(row0 + r) * CG + c] = acc[r];
    }
}

__global__ void __launch_bounds__(256) gemm1_kernel(const float* __restrict__ x,
                                                    const float* __restrict__ W1,
                                                    const float* __restrict__ asrc,
                                                    const float* __restrict__ adst) {
    float4 acc[4];
    int row0, c;
    gemm_core<FIN, H1DIM>(x, W1, g_h1, acc, row0, c);

    float4 a1 = ((const float4*)asrc)[c];
    float4 d1 = ((const float4*)adst)[c];
    int head = c >> 2;
#pragma unroll
    for (int r = 0; r < 4; r++) {
        float ta = acc[r].x * a1.x + acc[r].y * a1.y + acc[r].z * a1.z + acc[r].w * a1.w;
        float td = acc[r].x * d1.x + acc[r].y * d1.y + acc[r].z * d1.z + acc[r].w * d1.w;
        ta += __shfl_xor_sync(0xffffffffu, ta, 1, 4);
        ta += __shfl_xor_sync(0xffffffffu, ta, 2, 4);
        td += __shfl_xor_sync(0xffffffffu, td, 1, 4);
        td += __shfl_xor_sync(0xffffffffu, td, 2, 4);
        if ((c & 3) == 0 && row0 < NN) {
            g_as1[(row0 + r) * 4 + head] = ta;
            g_ad1[(row0 + r) * 4 + head] = td;
        }
    }
}

__global__ void __launch_bounds__(256) gemm2_kernel(const float* __restrict__ W2,
                                                    const float* __restrict__ asrc,
                                                    const float* __restrict__ adst) {
    float4 acc[4];
    int row0, c;
    gemm_core<H1DIM, CC>(g_hact, W2, g_h2, acc, row0, c);

    float4 a2 = ((const float4*)asrc)[c];
    float4 d2 = ((const float4*)adst)[c];
#pragma unroll
    for (int r = 0; r < 4; r++) {
        float ta = acc[r].x * a2.x + acc[r].y * a2.y + acc[r].z * a2.z + acc[r].w * a2.w;
        float td = acc[r].x * d2.x + acc[r].y * d2.y + acc[r].z * d2.z + acc[r].w * d2.w;
        ta += __shfl_xor_sync(0xffffffffu, ta, 1, 4);
        ta += __shfl_xor_sync(0xffffffffu, ta, 2, 4);
        td += __shfl_xor_sync(0xffffffffu, td, 1, 4);
        td += __shfl_xor_sync(0xffffffffu, td, 2, 4);
        if ((c & 3) == 0 && row0 < NN) {
            g_as2[row0 + r] = ta;
            g_ad2[row0 + r] = td;
        }
    }
}

// ---------------- layer-1 softmax + aggregation ------------------------------
// Half-warp (16 lanes) per dst; 2 dsts per warp; each lane owns one float4
// column group (16 groups = 64 floats). No cross-lane accumulator reduce.
__global__ void __launch_bounds__(256) gat_agg1_kernel(const float* __restrict__ b1) {
    __shared__ float4 sh_ex[8][32];
    __shared__ int    sh_s[8][32];
    int warp = threadIdx.x >> 5, lane = threadIdx.x & 31;
    int half = lane >> 4, hl = lane & 15;
    int myh = hl >> 2;
    int dn = (blockIdx.x * 8 + warp) * 2 + half;   // 6250*16 = 100000 exactly

    const float4* as1v = (const float4*)g_as1;
    const float4* ad1v = (const float4*)g_ad1;
    const float4* h1v4 = (const float4*)g_h1;

    float4 ad4 = ad1v[dn];
    int row = g_rowptr[dn];
    int deg = g_rowptr[dn + 1] - row;
    int degmax = max(deg, __shfl_xor_sync(0xffffffffu, deg, 16));
    float4 den = make_float4(0.f, 0.f, 0.f, 0.f);
    float4 acc = make_float4(0.f, 0.f, 0.f, 0.f);
    int bs = half * 16;

    for (int base = 0; base < degmax; base += 16) {
        int j = base + hl;
        bool valid = j < deg;
        int idx = row + (valid ? j : 0);
        idx = idx < EE ? idx : EE - 1;
        int s = g_csr[idx];
        float4 ex4 = make_float4(0.f, 0.f, 0.f, 0.f);
        if (valid) {
            float4 as4 = as1v[s];
            ex4.x = __expf(lrelu(as4.x + ad4.x));
            ex4.y = __expf(lrelu(as4.y + ad4.y));
            ex4.z = __expf(lrelu(as4.z + ad4.z));
            ex4.w = __expf(lrelu(as4.w + ad4.w));
            den.x += ex4.x; den.y += ex4.y; den.z += ex4.z; den.w += ex4.w;
        }
        sh_s[warp][lane] = s;
        sh_ex[warp][lane] = ex4;
        __syncwarp();

        int cnt = deg - base;
        cnt = cnt < 0 ? 0 : (cnt > 16 ? 16 : cnt);
        int e = 0;
        for (; e + 2 <= cnt; e += 2) {
            int s0 = sh_s[warp][bs + e];
            int s1 = sh_s[warp][bs + e + 1];
            float x0 = ((const float*)&sh_ex[warp][bs + e])[myh];
            float x1 = ((const float*)&sh_ex[warp][bs + e + 1])[myh];
            float4 h0 = h1v4[s0 * 16 + hl];
            float4 h1r = h1v4[s1 * 16 + hl];
            acc.x += x0 * h0.x + x1 * h1r.x;
            acc.y += x0 * h0.y + x1 * h1r.y;
            acc.z += x0 * h0.z + x1 * h1r.z;
            acc.w += x0 * h0.w + x1 * h1r.w;
        }
        if (e < cnt) {
            int s0 = sh_s[warp][bs + e];
            float x0 = ((const float*)&sh_ex[warp][bs + e])[myh];
            float4 h0 = h1v4[s0 * 16 + hl];
            acc.x += x0 * h0.x; acc.y += x0 * h0.y;
            acc.z += x0 * h0.z; acc.w += x0 * h0.w;
        }
        __syncwarp();
    }

    // denominator reduce within the 16-lane half
#pragma unroll
    for (int o = 8; o; o >>= 1) {
        den.x += __shfl_xor_sync(0xffffffffu, den.x, o, 16);
        den.y += __shfl_xor_sync(0xffffffffu, den.y, o, 16);
        den.z += __shfl_xor_sync(0xffffffffu, den.z, o, 16);
        den.w += __shfl_xor_sync(0xffffffffu, den.w, o, 16);
    }

    // self loop
    float4 asd = as1v[dn];
    float4 exs;
    exs.x = __expf(lrelu(asd.x + ad4.x));
    exs.y = __expf(lrelu(asd.y + ad4.y));
    exs.z = __expf(lrelu(asd.z + ad4.z));
    exs.w = __expf(lrelu(asd.w + ad4.w));
    den.x += exs.x; den.y += exs.y; den.z += exs.z; den.w += exs.w;

    float exm_self = sel4(exs, myh);
    float4 hd = h1v4[dn * 16 + hl];
    acc.x += exm_self * hd.x; acc.y += exm_self * hd.y;
    acc.z += exm_self * hd.z; acc.w += exm_self * hd.w;

    float inv = 1.f / (sel4(den, myh) + 1e-16f);
    float4 bv = ((const float4*)b1)[hl];
    float4 o;
    o.x = acc.x * inv + bv.x;
    o.y = acc.y * inv + bv.y;
    o.z = acc.z * inv + bv.z;
    o.w = acc.w * inv + bv.w;
    o.x = o.x > 0.f ? o.x : expm1f(o.x);
    o.y = o.y > 0.f ? o.y : expm1f(o.y);
    o.z = o.z > 0.f ? o.z : expm1f(o.z);
    o.w = o.w > 0.f ? o.w : expm1f(o.w);
    ((float4*)g_hact)[dn * 16 + hl] = o;
}

// ---------------- layer-2 softmax + aggregation ------------------------------
__global__ void __launch_bounds__(256) gat_agg2_kernel(const float* __restrict__ b2,
                                                       float* __restrict__ out) {
    __shared__ int   sh_s[8][32];
    __shared__ float sh_ex[8][32];
    int warp = threadIdx.x >> 5, lane = threadIdx.x & 31;
    int half = lane >> 4, hl = lane & 15;
    int dn = (blockIdx.x * 8 + warp) * 2 + half;

    float ad = g_ad2[dn];
    int row = g_rowptr[dn];
    int deg = g_rowptr[dn + 1] - row;
    int degmax = max(deg, __shfl_xor_sync(0xffffffffu, deg, 16));
    float den = 0.f;
    float a0 = 0.f, a1 = 0.f;
    int bs = half * 16;

    for (int base = 0; base < degmax; base += 16) {
        int j = base + hl;
        bool valid = j < deg;
        int idx = row + (valid ? j : 0);
        idx = idx < EE ? idx : EE - 1;
        int s = g_csr[idx];
        float ex = 0.f;
        if (valid) {
            ex = __expf(lrelu(g_as2[s] + ad));
            den += ex;
        }
        sh_s[warp][lane] = s;
        sh_ex[warp][lane] = ex;
        __syncwarp();

        int cnt = deg - base;
        cnt = cnt < 0 ? 0 : (cnt > 16 ? 16 : cnt);
        int jj = 0;
        for (; jj + 2 <= cnt; jj += 2) {
            int s0 = sh_s[warp][bs + jj];
            int s1 = sh_s[warp][bs + jj + 1];
            float x0 = sh_ex[warp][bs + jj];
            float x1 = sh_ex[warp][bs + jj + 1];
            a0 += x0 * g_h2[s0 * 16 + hl];
            a1 += x1 * g_h2[s1 * 16 + hl];
        }
        if (jj < cnt) {
            int s0 = sh_s[warp][bs + jj];
            float x0 = sh_ex[warp][bs + jj];
            a0 += x0 * g_h2[s0 * 16 + hl];
        }
        __syncwarp();
    }
    float acc = a0 + a1;
#pragma unroll
    for (int o = 8; o; o >>= 1) den += __shfl_xor_sync(0xffffffffu, den, o, 16);

    float exs = __expf(lrelu(g_as2[dn] + ad));
    den += exs;
    acc += exs * g_h2[dn * 16 + hl];
    out[dn * 16 + hl] = acc / (den + 1e-16f) + b2[hl];
}

// ---------------- launch ------------------------------------------------------
extern "C" void kernel_launch(void* const* d_in, const int* in_sizes, int n_in,
                              void* d_out, int out_size) {
    const float* x      = (const float*)d_in[0];
    const void*  ei     = d_in[1];
    const float* W1     = (const float*)d_in[2];
    const float* a_src1 = (const float*)d_in[3];
    const float* a_dst1 = (const float*)d_in[4];
    const float* b1     = (const float*)d_in[5];
    const float* W2     = (const float*)d_in[6];
    const float* a_src2 = (const float*)d_in[7];
    const float* a_dst2 = (const float*)d_in[8];
    const float* b2     = (const float*)d_in[9];
    float* out = (float*)d_out;

    (void)in_sizes; (void)n_in; (void)out_size;

    const int nThreads = 256;
    const int nBlocksN = (NN + nThreads - 1) / nThreads;
    const int nBlocksE = (EE + nThreads - 1) / nThreads;

    // Fork a side stream for the CSR build so it overlaps gemm1.
    cudaStream_t s2;
    cudaStreamCreateWithFlags(&s2, cudaStreamNonBlocking);
    cudaEvent_t eFork, eJoin;
    cudaEventCreateWithFlags(&eFork, cudaEventDisableTiming);
    cudaEventCreateWithFlags(&eJoin, cudaEventDisableTiming);

    cudaEventRecord(eFork, 0);
    cudaStreamWaitEvent(s2, eFork, 0);

    // CSR chain on s2
    probe_kernel<<<1, 32, 0, s2>>>((const int*)ei);
    zero_deg_kernel<<<nBlocksN, nThreads, 0, s2>>>();
    hist_kernel<<<nBlocksE, nThreads, 0, s2>>>(ei);
    scanA_kernel<<<NB2, 1024, 0, s2>>>();
    scanB_kernel<<<1, 32, 0, s2>>>();
    scanC_kernel<<<nBlocksN, nThreads, 0, s2>>>();
    scatter_kernel<<<nBlocksE, nThreads, 0, s2>>>(ei);
    cudaEventRecord(eJoin, s2);

    // gemm1 on main stream, concurrent with CSR build
    gemm1_kernel<<<(NN + 63) / 64, 256>>>(x, W1, a_src1, a_dst1);

    cudaStreamWaitEvent(0, eJoin, 0);

    gat_agg1_kernel<<<(NN + 15) / 16, 256>>>(b1);
    gemm2_kernel<<<(NN + 255) / 256, 256>>>(W2, a_src2, a_dst2);
    gat_agg2_kernel<<<(NN + 15) / 16, 256>>>(b2, out);

    cudaEventDestroy(eFork);
    cudaEventDestroy(eJoin);
    cudaStreamDestroy(s2);
}

// round 5
// speedup vs baseline: 1.4895x; 1.0475x over previous
#include <cuda_runtime.h>

#define NN 100000
#define EE 1000000
#define FIN 128
#define HID 16
#define HEADS 4
#define CC 16
#define H1DIM 64            // HEADS*HID
#define NB2 25              // ceil(NN/4096) scan blocks

typedef unsigned long long u64;

// ---------------- scratch (static device globals; no allocation) -------------
__device__ int   g_idx64;           // 1 if edge_index is int64, 0 if int32
__device__ __align__(16) int g_deg[NN];
__device__ int   g_rowptr[NN + 1];
__device__ int   g_cursor[NN];
__device__ int   g_bsum[32];
__device__ int   g_boff[32];
__device__ int   g_csr[EE];
__device__ __align__(16) float g_h1[NN * H1DIM];
__device__ __align__(16) float g_as1[NN * 4];
__device__ __align__(16) float g_ad1[NN * 4];
__device__ __align__(16) float g_hact[NN * H1DIM];
__device__ __align__(16) float g_h2[NN * CC];
__device__ float g_as2[NN];
__device__ float g_ad2[NN];

// ---------------- f32x2 packed helpers ---------------------------------------
__device__ __forceinline__ u64 fma2(u64 a, u64 b, u64 c) {
    u64 d;
    asm("fma.rn.f32x2 %0, %1, %2, %3;" : "=l"(d) : "l"(a), "l"(b), "l"(c));
    return d;
}
__device__ __forceinline__ u64 mul2(u64 a, u64 b) {
    u64 d;
    asm("mul.rn.f32x2 %0, %1, %2;" : "=l"(d) : "l"(a), "l"(b));
    return d;
}
__device__ __forceinline__ u64 dup2(float s) {
    u64 d; unsigned u = __float_as_uint(s);
    asm("mov.b64 %0, {%1, %1};" : "=l"(d) : "r"(u));
    return d;
}
__device__ __forceinline__ float2 unpack2(u64 v) {
    unsigned lo, hi;
    asm("mov.b64 {%0, %1}, %2;" : "=r"(lo), "=r"(hi) : "l"(v));
    return make_float2(__uint_as_float(lo), __uint_as_float(hi));
}

__device__ __forceinline__ float lrelu(float x) { return x > 0.f ? x : 0.2f * x; }

__device__ __forceinline__ int clampN(int v) {
    return v < 0 ? 0 : (v >= NN ? NN - 1 : v);
}

__device__ __forceinline__ int load_idx(const void* __restrict__ ei, int pos, int is64) {
    if (is64) return clampN((int)((const long long*)ei)[pos]);
    return clampN(((const int*)ei)[pos]);
}

__device__ __forceinline__ float sel4(float4 v, int k) {
    return k == 0 ? v.x : k == 1 ? v.y : k == 2 ? v.z : v.w;
}

// ---------------- dtype probe (warp-parallel) --------------------------------
__global__ void probe_kernel(const int* __restrict__ w) {
    int ok = 1;
    for (int k = threadIdx.x; k < 1024; k += 32) ok &= (w[2 * k + 1] == 0);
    ok = __all_sync(0xffffffffu, ok != 0);
    if (threadIdx.x == 0) g_idx64 = ok;
}

// ---------------- CSR build --------------------------------------------------
__global__ void zero_deg_kernel() {
    int i = blockIdx.x * blockDim.x + threadIdx.x;
    if (i < NN) g_deg[i] = 0;
}

__global__ void hist_kernel(const void* __restrict__ ei) {
    int e = blockIdx.x * blockDim.x + threadIdx.x;
    int is64 = g_idx64;
    if (e < EE) atomicAdd(&g_deg[load_idx(ei, EE + e, is64)], 1);
}

// shfl-based scan: 4 elements/thread, 4096/block, 25 blocks.
__global__ void __launch_bounds__(1024) scanA_kernel() {
    __shared__ int warp_sums[32];
    int t = threadIdx.x;
    int base = blockIdx.x * 4096 + t * 4;
    int4 v = make_int4(0, 0, 0, 0);
    if (base + 3 < NN) {
        v = *(const int4*)&g_deg[base];
    } else {
        if (base + 0 < NN) v.x = g_deg[base + 0];
        if (base + 1 < NN) v.y = g_deg[base + 1];
        if (base + 2 < NN) v.z = g_deg[base + 2];
        if (base + 3 < NN) v.w = g_deg[base + 3];
    }
    int s1 = v.x, s2 = s1 + v.y, s3 = s2 + v.z, s4 = s3 + v.w;
    int lane = t & 31, wid = t >> 5;
    int ws = s4;
#pragma unroll
    for (int o = 1; o < 32; o <<= 1) {
        int u = __shfl_up_sync(0xffffffffu, ws, o);
        if (lane >= o) ws += u;
    }
    if (lane == 31) warp_sums[wid] = ws;
    __syncthreads();
    if (wid == 0) {
        int x = warp_sums[lane];
#pragma unroll
        for (int o = 1; o < 32; o <<= 1) {
            int u = __shfl_up_sync(0xffffffffu, x, o);
            if (lane >= o) x += u;
        }
        warp_sums[lane] = x;
    }
    __syncthreads();
    int excl = (wid ? warp_sums[wid - 1] : 0) + ws - s4;
    if (base + 0 < NN) g_rowptr[base + 1] = excl + s1;
    if (base + 1 < NN) g_rowptr[base + 2] = excl + s2;
    if (base + 2 < NN) g_rowptr[base + 3] = excl + s3;
    if (base + 3 < NN) g_rowptr[base + 4] = excl + s4;
    if (t == 0) g_bsum[blockIdx.x] = warp_sums[31];
}

__global__ void scanB_kernel() {
    int lane = threadIdx.x;
    int v = (lane < NB2) ? g_bsum[lane] : 0;
    int x = v;
#pragma unroll
    for (int o = 1; o < 32; o <<= 1) {
        int u = __shfl_up_sync(0xffffffffu, x, o);
        if (lane >= o) x += u;
    }
    if (lane < NB2) g_boff[lane] = x - v;   // exclusive
}

__global__ void scanC_kernel() {
    int i = blockIdx.x * blockDim.x + threadIdx.x;
    if (i == 0) g_rowptr[0] = 0;
    if (i < NN) {
        int r = g_rowptr[i + 1] + g_boff[i >> 12];
        g_rowptr[i + 1] = r;
        g_cursor[i] = r - g_deg[i];
    }
}

__global__ void scatter_kernel(const void* __restrict__ ei) {
    int e = blockIdx.x * blockDim.x + threadIdx.x;
    int is64 = g_idx64;
    if (e < EE) {
        int s = load_idx(ei, e, is64);
        int d = load_idx(ei, EE + e, is64);
        int pos = atomicAdd(&g_cursor[d], 1);
        g_csr[pos] = s;
    }
}

// ---------------- GEMM core (f32x2 packed accumulators) ----------------------
// acc column-packed: accL[r] = (col0,col1), accH[r] = (col2,col3) of float4 group c.
template <int K, int M>
__device__ __forceinline__ void gemm_core(const float* __restrict__ X,
                                          const float* __restrict__ W,
                                          float* __restrict__ Y,
                                          u64 accL[4], u64 accH[4],
                                          int& row0_out, int& c_out) {
    constexpr int CG = M / 4;
    constexpr int SLOTS = 256 / CG;
    __shared__ ulonglong2 Wsh[K * CG];
    int tid = threadIdx.x;
    for (int i = tid; i < K * CG; i += 256) Wsh[i] = ((const ulonglong2*)W)[i];
    __syncthreads();

    int c = tid % CG;
    int slot = tid / CG;
    int row0 = (blockIdx.x * SLOTS + slot) * 4;
    int rowL = (row0 < NN) ? row0 : 0;
    row0_out = row0;
    c_out = c;

    const float4* Xv = (const float4*)X;
#pragma unroll
    for (int r = 0; r < 4; r++) { accL[r] = 0ull; accH[r] = 0ull; }

#pragma unroll 2
    for (int k4 = 0; k4 < K / 4; k4++) {
        ulonglong2 w0 = Wsh[(4 * k4 + 0) * CG + c];
        ulonglong2 w1 = Wsh[(4 * k4 + 1) * CG + c];
        ulonglong2 w2 = Wsh[(4 * k4 + 2) * CG + c];
        ulonglong2 w3 = Wsh[(4 * k4 + 3) * CG + c];
#pragma unroll
        for (int r = 0; r < 4; r++) {
            float4 xv = Xv[(rowL + r) * (K / 4) + k4];
            u64 dx = dup2(xv.x), dy = dup2(xv.y), dz = dup2(xv.z), dw = dup2(xv.w);
            accL[r] = fma2(dx, w0.x, accL[r]); accH[r] = fma2(dx, w0.y, accH[r]);
            accL[r] = fma2(dy, w1.x, accL[r]); accH[r] = fma2(dy, w1.y, accH[r]);
            accL[r] = fma2(dz, w2.x, accL[r]); accH[r] = fma2(dz, w2.y, accH[r]);
            accL[r] = fma2(dw, w3.x, accL[r]); accH[r] = fma2(dw, w3.y, accH[r]);
        }
    }
    if (row0 < NN) {
        ulonglong2* Yv = (ulonglong2*)Y;
#pragma unroll
        for (int r = 0; r < 4; r++) {
            ulonglong2 o; o.x = accL[r]; o.y = accH[r];
            Yv[(row0 + r) * CG + c] = o;
        }
    }
}

// fused attn epilogue: dot(acc, a) via packed mul/fma then horizontal add.
__device__ __forceinline__ float dot_packed(u64 aL, u64 aH, ulonglong2 v) {
    u64 t = mul2(aL, v.x);
    t = fma2(aH, v.y, t);
    float2 f = unpack2(t);
    return f.x + f.y;
}

__global__ void __launch_bounds__(256) gemm1_kernel(const float* __restrict__ x,
                                                    const float* __restrict__ W1,
                                                    const float* __restrict__ asrc,
                                                    const float* __restrict__ adst) {
    u64 accL[4], accH[4];
    int row0, c;
    gemm_core<FIN, H1DIM>(x, W1, g_h1, accL, accH, row0, c);

    ulonglong2 a1 = ((const ulonglong2*)asrc)[c];
    ulonglong2 d1 = ((const ulonglong2*)adst)[c];
    int head = c >> 2;
#pragma unroll
    for (int r = 0; r < 4; r++) {
        float ta = dot_packed(accL[r], accH[r], a1);
        float td = dot_packed(accL[r], accH[r], d1);
        ta += __shfl_xor_sync(0xffffffffu, ta, 1, 4);
        ta += __shfl_xor_sync(0xffffffffu, ta, 2, 4);
        td += __shfl_xor_sync(0xffffffffu, td, 1, 4);
        td += __shfl_xor_sync(0xffffffffu, td, 2, 4);
        if ((c & 3) == 0 && row0 < NN) {
            g_as1[(row0 + r) * 4 + head] = ta;
            g_ad1[(row0 + r) * 4 + head] = td;
        }
    }
}

__global__ void __launch_bounds__(256) gemm2_kernel(const float* __restrict__ W2,
                                                    const float* __restrict__ asrc,
                                                    const float* __restrict__ adst) {
    u64 accL[4], accH[4];
    int row0, c;
    gemm_core<H1DIM, CC>(g_hact, W2, g_h2, accL, accH, row0, c);

    ulonglong2 a2 = ((const ulonglong2*)asrc)[c];
    ulonglong2 d2 = ((const ulonglong2*)adst)[c];
#pragma unroll
    for (int r = 0; r < 4; r++) {
        float ta = dot_packed(accL[r], accH[r], a2);
        float td = dot_packed(accL[r], accH[r], d2);
        ta += __shfl_xor_sync(0xffffffffu, ta, 1, 4);
        ta += __shfl_xor_sync(0xffffffffu, ta, 2, 4);
        td += __shfl_xor_sync(0xffffffffu, td, 1, 4);
        td += __shfl_xor_sync(0xffffffffu, td, 2, 4);
        if ((c & 3) == 0 && row0 < NN) {
            g_as2[row0 + r] = ta;
            g_ad2[row0 + r] = td;
        }
    }
}

// ---------------- layer-1 softmax + aggregation ------------------------------
// Half-warp (16 lanes) per dst; 2 dsts/warp; lane owns one float4 column group.
// smem per (head, edge): float2{src_bits, exp_coeff} so the consumer fetches
// an edge PAIR with one LDS.128; message FMA in packed f32x2.
__global__ void __launch_bounds__(256) gat_agg1_kernel(const float* __restrict__ b1) {
    __shared__ __align__(16) float2 sh_p[8][2][4][16];   // [warp][half][head][edge]
    int warp = threadIdx.x >> 5, lane = threadIdx.x & 31;
    int half = lane >> 4, hl = lane & 15;
    int myh = hl >> 2;
    int dn = (blockIdx.x * 8 + warp) * 2 + half;   // 6250*16 = 100000 exactly

    const float4* as1v = (const float4*)g_as1;
    const float4* ad1v = (const float4*)g_ad1;
    const ulonglong2* h1u = (const ulonglong2*)g_h1;   // row = 16 ull2

    float4 ad4 = ad1v[dn];
    int row = g_rowptr[dn];
    int deg = g_rowptr[dn + 1] - row;
    int degmax = max(deg, __shfl_xor_sync(0xffffffffu, deg, 16));
    float4 den = make_float4(0.f, 0.f, 0.f, 0.f);
    u64 accL = 0ull, accH = 0ull;

    for (int base = 0; base < degmax; base += 16) {
        int j = base + hl;
        bool valid = j < deg;
        int idx = row + (valid ? j : 0);
        idx = idx < EE ? idx : EE - 1;
        int s = g_csr[idx];
        float4 ex4 = make_float4(0.f, 0.f, 0.f, 0.f);
        if (valid) {
            float4 as4 = as1v[s];
            ex4.x = __expf(lrelu(as4.x + ad4.x));
            ex4.y = __expf(lrelu(as4.y + ad4.y));
            ex4.z = __expf(lrelu(as4.z + ad4.z));
            ex4.w = __expf(lrelu(as4.w + ad4.w));
            den.x += ex4.x; den.y += ex4.y; den.z += ex4.z; den.w += ex4.w;
        }
        float sb = __int_as_float(s);
        sh_p[warp][half][0][hl] = make_float2(sb, ex4.x);
        sh_p[warp][half][1][hl] = make_float2(sb, ex4.y);
        sh_p[warp][half][2][hl] = make_float2(sb, ex4.z);
        sh_p[warp][half][3][hl] = make_float2(sb, ex4.w);
        __syncwarp();

        int cnt = deg - base;
        cnt = cnt < 0 ? 0 : (cnt > 16 ? 16 : cnt);
        const float4* prow = (const float4*)&sh_p[warp][half][myh][0];
        // pairs; the possible overshoot slot has x==0 so it contributes nothing
        for (int e = 0; e < cnt; e += 2) {
            float4 p = prow[e >> 1];               // {s0,x0,s1,x1}
            int s0 = __float_as_int(p.x);
            int s1 = __float_as_int(p.z);
            ulonglong2 h0 = h1u[s0 * 16 + hl];
            ulonglong2 h1r = h1u[s1 * 16 + hl];
            u64 d0 = dup2(p.y), d1 = dup2(p.w);
            accL = fma2(d0, h0.x, accL); accH = fma2(d0, h0.y, accH);
            accL = fma2(d1, h1r.x, accL); accH = fma2(d1, h1r.y, accH);
        }
        __syncwarp();
    }

    // denominator reduce within the 16-lane half
#pragma unroll
    for (int o = 8; o; o >>= 1) {
        den.x += __shfl_xor_sync(0xffffffffu, den.x, o, 16);
        den.y += __shfl_xor_sync(0xffffffffu, den.y, o, 16);
        den.z += __shfl_xor_sync(0xffffffffu, den.z, o, 16);
        den.w += __shfl_xor_sync(0xffffffffu, den.w, o, 16);
    }

    // self loop
    float4 asd = as1v[dn];
    float4 exs;
    exs.x = __expf(lrelu(asd.x + ad4.x));
    exs.y = __expf(lrelu(asd.y + ad4.y));
    exs.z = __expf(lrelu(asd.z + ad4.z));
    exs.w = __expf(lrelu(asd.w + ad4.w));
    den.x += exs.x; den.y += exs.y; den.z += exs.z; den.w += exs.w;

    float exm_self = sel4(exs, myh);
    ulonglong2 hdp = h1u[dn * 16 + hl];
    u64 ds = dup2(exm_self);
    accL = fma2(ds, hdp.x, accL);
    accH = fma2(ds, hdp.y, accH);

    float2 aL = unpack2(accL), aH = unpack2(accH);
    float inv = 1.f / (sel4(den, myh) + 1e-16f);
    float4 bv = ((const float4*)b1)[hl];
    float4 o;
    o.x = aL.x * inv + bv.x;
    o.y = aL.y * inv + bv.y;
    o.z = aH.x * inv + bv.z;
    o.w = aH.y * inv + bv.w;
    o.x = o.x > 0.f ? o.x : expm1f(o.x);
    o.y = o.y > 0.f ? o.y : expm1f(o.y);
    o.z = o.z > 0.f ? o.z : expm1f(o.z);
    o.w = o.w > 0.f ? o.w : expm1f(o.w);
    ((float4*)g_hact)[dn * 16 + hl] = o;
}

// ---------------- layer-2 softmax + aggregation ------------------------------
__global__ void __launch_bounds__(256) gat_agg2_kernel(const float* __restrict__ b2,
                                                       float* __restrict__ out) {
    __shared__ int   sh_s[8][32];
    __shared__ float sh_ex[8][32];
    int warp = threadIdx.x >> 5, lane = threadIdx.x & 31;
    int half = lane >> 4, hl = lane & 15;
    int dn = (blockIdx.x * 8 + warp) * 2 + half;

    float ad = g_ad2[dn];
    int row = g_rowptr[dn];
    int deg = g_rowptr[dn + 1] - row;
    int degmax = max(deg, __shfl_xor_sync(0xffffffffu, deg, 16));
    float den = 0.f;
    float a0 = 0.f, a1 = 0.f;
    int bs = half * 16;

    for (int base = 0; base < degmax; base += 16) {
        int j = base + hl;
        bool valid = j < deg;
        int idx = row + (valid ? j : 0);
        idx = idx < EE ? idx : EE - 1;
        int s = g_csr[idx];
        float ex = 0.f;
        if (valid) {
            ex = __expf(lrelu(g_as2[s] + ad));
            den += ex;
        }
        sh_s[warp][lane] = s;
        sh_ex[warp][lane] = ex;
        __syncwarp();

        int cnt = deg - base;
        cnt = cnt < 0 ? 0 : (cnt > 16 ? 16 : cnt);
        int jj = 0;
        for (; jj + 2 <= cnt; jj += 2) {
            int s0 = sh_s[warp][bs + jj];
            int s1 = sh_s[warp][bs + jj + 1];
            float x0 = sh_ex[warp][bs + jj];
            float x1 = sh_ex[warp][bs + jj + 1];
            a0 += x0 * g_h2[s0 * 16 + hl];
            a1 += x1 * g_h2[s1 * 16 + hl];
        }
        if (jj < cnt) {
            int s0 = sh_s[warp][bs + jj];
            float x0 = sh_ex[warp][bs + jj];
            a0 += x0 * g_h2[s0 * 16 + hl];
        }
        __syncwarp();
    }
    float acc = a0 + a1;
#pragma unroll
    for (int o = 8; o; o >>= 1) den += __shfl_xor_sync(0xffffffffu, den, o, 16);

    float exs = __expf(lrelu(g_as2[dn] + ad));
    den += exs;
    acc += exs * g_h2[dn * 16 + hl];
    out[dn * 16 + hl] = acc / (den + 1e-16f) + b2[hl];
}

// ---------------- launch ------------------------------------------------------
extern "C" void kernel_launch(void* const* d_in, const int* in_sizes, int n_in,
                              void* d_out, int out_size) {
    const float* x      = (const float*)d_in[0];
    const void*  ei     = d_in[1];
    const float* W1     = (const float*)d_in[2];
    const float* a_src1 = (const float*)d_in[3];
    const float* a_dst1 = (const float*)d_in[4];
    const float* b1     = (const float*)d_in[5];
    const float* W2     = (const float*)d_in[6];
    const float* a_src2 = (const float*)d_in[7];
    const float* a_dst2 = (const float*)d_in[8];
    const float* b2     = (const float*)d_in[9];
    float* out = (float*)d_out;

    (void)in_sizes; (void)n_in; (void)out_size;

    const int nThreads = 256;
    const int nBlocksN = (NN + nThreads - 1) / nThreads;
    const int nBlocksE = (EE + nThreads - 1) / nThreads;

    // Fork a side stream for the CSR build so it overlaps gemm1.
    cudaStream_t s2;
    cudaStreamCreateWithFlags(&s2, cudaStreamNonBlocking);
    cudaEvent_t eFork, eJoin;
    cudaEventCreateWithFlags(&eFork, cudaEventDisableTiming);
    cudaEventCreateWithFlags(&eJoin, cudaEventDisableTiming);

    cudaEventRecord(eFork, 0);
    cudaStreamWaitEvent(s2, eFork, 0);

    // CSR chain on s2
    probe_kernel<<<1, 32, 0, s2>>>((const int*)ei);
    zero_deg_kernel<<<nBlocksN, nThreads, 0, s2>>>();
    hist_kernel<<<nBlocksE, nThreads, 0, s2>>>(ei);
    scanA_kernel<<<NB2, 1024, 0, s2>>>();
    scanB_kernel<<<1, 32, 0, s2>>>();
    scanC_kernel<<<nBlocksN, nThreads, 0, s2>>>();
    scatter_kernel<<<nBlocksE, nThreads, 0, s2>>>(ei);
    cudaEventRecord(eJoin, s2);

    // gemm1 on main stream, concurrent with CSR build
    gemm1_kernel<<<(NN + 63) / 64, 256>>>(x, W1, a_src1, a_dst1);

    cudaStreamWaitEvent(0, eJoin, 0);

    gat_agg1_kernel<<<(NN + 15) / 16, 256>>>(b1);
    gemm2_kernel<<<(NN + 255) / 256, 256>>>(W2, a_src2, a_dst2);
    gat_agg2_kernel<<<(NN + 15) / 16, 256>>>(b2, out);

    cudaEventDestroy(eFork);
    cudaEventDestroy(eJoin);
    cudaStreamDestroy(s2);
}

// round 6
// speedup vs baseline: 1.4927x; 1.0022x over previous
#include <cuda_runtime.h>

#define NN 100000
#define EE 1000000
#define FIN 128
#define HID 16
#define HEADS 4
#define CC 16
#define H1DIM 64            // HEADS*HID
#define NB2 25              // ceil(NN/4096) scan blocks

typedef unsigned long long u64;

// ---------------- scratch (static device globals; no allocation) -------------
__device__ __align__(16) int g_deg[NN];
__device__ int   g_rowptr[NN + 1];
__device__ int   g_cursor[NN];
__device__ int   g_bsum[32];
__device__ int   g_boff[32];
__device__ int   g_csr[EE];
__device__ __align__(16) float g_h1[NN * H1DIM];
__device__ __align__(16) float g_as1[NN * 4];
__device__ __align__(16) float g_ad1[NN * 4];
__device__ __align__(16) float g_h2[NN * CC];
__device__ float g_as2[NN];
__device__ float g_ad2[NN];

// ---------------- f32x2 packed helpers ---------------------------------------
__device__ __forceinline__ u64 fma2(u64 a, u64 b, u64 c) {
    u64 d;
    asm("fma.rn.f32x2 %0, %1, %2, %3;" : "=l"(d) : "l"(a), "l"(b), "l"(c));
    return d;
}
__device__ __forceinline__ u64 mul2(u64 a, u64 b) {
    u64 d;
    asm("mul.rn.f32x2 %0, %1, %2;" : "=l"(d) : "l"(a), "l"(b));
    return d;
}
__device__ __forceinline__ u64 dup2(float s) {
    u64 d; unsigned u = __float_as_uint(s);
    asm("mov.b64 %0, {%1, %1};" : "=l"(d) : "r"(u));
    return d;
}
__device__ __forceinline__ float2 unpack2(u64 v) {
    unsigned lo, hi;
    asm("mov.b64 {%0, %1}, %2;" : "=r"(lo), "=r"(hi) : "l"(v));
    return make_float2(__uint_as_float(lo), __uint_as_float(hi));
}

__device__ __forceinline__ float lrelu(float x) { return x > 0.f ? x : 0.2f * x; }

__device__ __forceinline__ int clampN(int v) {
    return v < 0 ? 0 : (v >= NN ? NN - 1 : v);
}

__device__ __forceinline__ int load_idx(const void* __restrict__ ei, int pos, int is64) {
    if (is64) return clampN((int)((const long long*)ei)[pos]);
    return clampN(((const int*)ei)[pos]);
}

__device__ __forceinline__ float sel4(float4 v, int k) {
    return k == 0 ? v.x : k == 1 ? v.y : k == 2 ? v.z : v.w;
}

// Per-block dtype probe: int64 data has zero high words; int32 graph indices
// make 8 consecutive zero odd-words astronomically unlikely (~1e-40).
__device__ __forceinline__ int block_probe64(const int* __restrict__ w, int* s_flag) {
    if (threadIdx.x == 0) {
        int ok = 1;
#pragma unroll
        for (int i = 1; i < 16; i += 2) ok &= (w[i] == 0);
        *s_flag = ok;
    }
    __syncthreads();
    return *s_flag;
}

// ---------------- CSR build --------------------------------------------------
__global__ void zero_deg_kernel() {
    int i = blockIdx.x * blockDim.x + threadIdx.x;
    if (i < NN) g_deg[i] = 0;
}

__global__ void hist_kernel(const void* __restrict__ ei) {
    __shared__ int s_is64;
    int is64 = block_probe64((const int*)ei, &s_is64);
    int e = blockIdx.x * blockDim.x + threadIdx.x;
    if (e < EE) atomicAdd(&g_deg[load_idx(ei, EE + e, is64)], 1);
}

// shfl-based scan: 4 elements/thread, 4096/block, 25 blocks.
__global__ void __launch_bounds__(1024) scanA_kernel() {
    __shared__ int warp_sums[32];
    int t = threadIdx.x;
    int base = blockIdx.x * 4096 + t * 4;
    int4 v = make_int4(0, 0, 0, 0);
    if (base + 3 < NN) {
        v = *(const int4*)&g_deg[base];
    } else {
        if (base + 0 < NN) v.x = g_deg[base + 0];
        if (base + 1 < NN) v.y = g_deg[base + 1];
        if (base + 2 < NN) v.z = g_deg[base + 2];
        if (base + 3 < NN) v.w = g_deg[base + 3];
    }
    int s1 = v.x, s2 = s1 + v.y, s3 = s2 + v.z, s4 = s3 + v.w;
    int lane = t & 31, wid = t >> 5;
    int ws = s4;
#pragma unroll
    for (int o = 1; o < 32; o <<= 1) {
        int u = __shfl_up_sync(0xffffffffu, ws, o);
        if (lane >= o) ws += u;
    }
    if (lane == 31) warp_sums[wid] = ws;
    __syncthreads();
    if (wid == 0) {
        int x = warp_sums[lane];
#pragma unroll
        for (int o = 1; o < 32; o <<= 1) {
            int u = __shfl_up_sync(0xffffffffu, x, o);
            if (lane >= o) x += u;
        }
        warp_sums[lane] = x;
    }
    __syncthreads();
    int excl = (wid ? warp_sums[wid - 1] : 0) + ws - s4;
    if (base + 0 < NN) g_rowptr[base + 1] = excl + s1;
    if (base + 1 < NN) g_rowptr[base + 2] = excl + s2;
    if (base + 2 < NN) g_rowptr[base + 3] = excl + s3;
    if (base + 3 < NN) g_rowptr[base + 4] = excl + s4;
    if (t == 0) g_bsum[blockIdx.x] = warp_sums[31];
}

__global__ void scanB_kernel() {
    int lane = threadIdx.x;
    int v = (lane < NB2) ? g_bsum[lane] : 0;
    int x = v;
#pragma unroll
    for (int o = 1; o < 32; o <<= 1) {
        int u = __shfl_up_sync(0xffffffffu, x, o);
        if (lane >= o) x += u;
    }
    if (lane < NB2) g_boff[lane] = x - v;   // exclusive
}

__global__ void scanC_kernel() {
    int i = blockIdx.x * blockDim.x + threadIdx.x;
    if (i == 0) g_rowptr[0] = 0;
    if (i < NN) {
        int r = g_rowptr[i + 1] + g_boff[i >> 12];
        g_rowptr[i + 1] = r;
        g_cursor[i] = r - g_deg[i];
    }
}

__global__ void scatter_kernel(const void* __restrict__ ei) {
    __shared__ int s_is64;
    int is64 = block_probe64((const int*)ei, &s_is64);
    int e = blockIdx.x * blockDim.x + threadIdx.x;
    if (e < EE) {
        int s = load_idx(ei, e, is64);
        int d = load_idx(ei, EE + e, is64);
        int pos = atomicAdd(&g_cursor[d], 1);
        g_csr[pos] = s;
    }
}

// ---------------- GEMM1 (f32x2 packed accumulators) + fused attn1 ------------
__global__ void __launch_bounds__(256) gemm1_kernel(const float* __restrict__ x,
                                                    const float* __restrict__ W1,
                                                    const float* __restrict__ asrc,
                                                    const float* __restrict__ adst) {
    constexpr int K = FIN, CG = H1DIM / 4, SLOTS = 256 / CG;
    __shared__ ulonglong2 Wsh[K * CG];
    int tid = threadIdx.x;
    for (int i = tid; i < K * CG; i += 256) Wsh[i] = ((const ulonglong2*)W1)[i];
    __syncthreads();

    int c = tid % CG;
    int slot = tid / CG;
    int row0 = (blockIdx.x * SLOTS + slot) * 4;
    int rowL = (row0 < NN) ? row0 : 0;

    const float4* Xv = (const float4*)x;
    u64 accL[4], accH[4];
#pragma unroll
    for (int r = 0; r < 4; r++) { accL[r] = 0ull; accH[r] = 0ull; }

#pragma unroll 2
    for (int k4 = 0; k4 < K / 4; k4++) {
        ulonglong2 w0 = Wsh[(4 * k4 + 0) * CG + c];
        ulonglong2 w1 = Wsh[(4 * k4 + 1) * CG + c];
        ulonglong2 w2 = Wsh[(4 * k4 + 2) * CG + c];
        ulonglong2 w3 = Wsh[(4 * k4 + 3) * CG + c];
#pragma unroll
        for (int r = 0; r < 4; r++) {
            float4 xv = Xv[(rowL + r) * (K / 4) + k4];
            u64 dx = dup2(xv.x), dy = dup2(xv.y), dz = dup2(xv.z), dw = dup2(xv.w);
            accL[r] = fma2(dx, w0.x, accL[r]); accH[r] = fma2(dx, w0.y, accH[r]);
            accL[r] = fma2(dy, w1.x, accL[r]); accH[r] = fma2(dy, w1.y, accH[r]);
            accL[r] = fma2(dz, w2.x, accL[r]); accH[r] = fma2(dz, w2.y, accH[r]);
            accL[r] = fma2(dw, w3.x, accL[r]); accH[r] = fma2(dw, w3.y, accH[r]);
        }
    }
    if (row0 < NN) {
        ulonglong2* Yv = (ulonglong2*)g_h1;
#pragma unroll
        for (int r = 0; r < 4; r++) {
            ulonglong2 o; o.x = accL[r]; o.y = accH[r];
            Yv[(row0 + r) * CG + c] = o;
        }
    }

    ulonglong2 a1 = ((const ulonglong2*)asrc)[c];
    ulonglong2 d1 = ((const ulonglong2*)adst)[c];
    int head = c >> 2;
#pragma unroll
    for (int r = 0; r < 4; r++) {
        u64 t = mul2(accL[r], a1.x); t = fma2(accH[r], a1.y, t);
        float2 f = unpack2(t);
        float ta = f.x + f.y;
        u64 t2 = mul2(accL[r], d1.x); t2 = fma2(accH[r], d1.y, t2);
        float2 f2 = unpack2(t2);
        float td = f2.x + f2.y;
        ta += __shfl_xor_sync(0xffffffffu, ta, 1, 4);
        ta += __shfl_xor_sync(0xffffffffu, ta, 2, 4);
        td += __shfl_xor_sync(0xffffffffu, td, 1, 4);
        td += __shfl_xor_sync(0xffffffffu, td, 2, 4);
        if ((c & 3) == 0 && row0 < NN) {
            g_as1[(row0 + r) * 4 + head] = ta;
            g_ad1[(row0 + r) * 4 + head] = td;
        }
    }
}

// ---------------- fused layer-1 agg + elu + gemm2 + attn2 --------------------
// Half-warp (16 lanes) per dst; 2 dsts/warp. After softmax-aggregating the
// hact row into smem, each lane computes one h2 column (hact·W2[:,hl]) and the
// width-16 reduce produces as2/ad2. g_hact round-trip and gemm2 kernel gone.
__global__ void __launch_bounds__(256) gat_agg1_fused_kernel(
        const float* __restrict__ b1, const float* __restrict__ W2,
        const float* __restrict__ asrc2, const float* __restrict__ adst2) {
    __shared__ __align__(16) float2 sh_p[8][2][4][16];   // [warp][half][head][edge]
    __shared__ __align__(16) float4 sh_hact[8][2][17];   // padded to dodge bank overlap
    __shared__ float W2sh[H1DIM * CC];                   // 4 KB
    int tid = threadIdx.x;
    for (int i = tid; i < H1DIM * CC; i += 256) W2sh[i] = W2[i];
    __syncthreads();

    int warp = tid >> 5, lane = tid & 31;
    int half = lane >> 4, hl = lane & 15;
    int myh = hl >> 2;
    int dn = (blockIdx.x * 8 + warp) * 2 + half;   // 6250*16 = 100000 exactly

    const float4* as1v = (const float4*)g_as1;
    const float4* ad1v = (const float4*)g_ad1;
    const ulonglong2* h1u = (const ulonglong2*)g_h1;

    float4 ad4 = ad1v[dn];
    int row = g_rowptr[dn];
    int deg = g_rowptr[dn + 1] - row;
    int degmax = max(deg, __shfl_xor_sync(0xffffffffu, deg, 16));
    float4 den = make_float4(0.f, 0.f, 0.f, 0.f);
    u64 accL = 0ull, accH = 0ull;

    for (int base = 0; base < degmax; base += 16) {
        int j = base + hl;
        bool valid = j < deg;
        int idx = row + (valid ? j : 0);
        idx = idx < EE ? idx : EE - 1;
        int s = g_csr[idx];
        float4 ex4 = make_float4(0.f, 0.f, 0.f, 0.f);
        if (valid) {
            float4 as4 = as1v[s];
            ex4.x = __expf(lrelu(as4.x + ad4.x));
            ex4.y = __expf(lrelu(as4.y + ad4.y));
            ex4.z = __expf(lrelu(as4.z + ad4.z));
            ex4.w = __expf(lrelu(as4.w + ad4.w));
            den.x += ex4.x; den.y += ex4.y; den.z += ex4.z; den.w += ex4.w;
        }
        float sb = __int_as_float(s);
        sh_p[warp][half][0][hl] = make_float2(sb, ex4.x);
        sh_p[warp][half][1][hl] = make_float2(sb, ex4.y);
        sh_p[warp][half][2][hl] = make_float2(sb, ex4.z);
        sh_p[warp][half][3][hl] = make_float2(sb, ex4.w);
        __syncwarp();

        int cnt = deg - base;
        cnt = cnt < 0 ? 0 : (cnt > 16 ? 16 : cnt);
        const float4* prow = (const float4*)&sh_p[warp][half][myh][0];
        for (int e = 0; e < cnt; e += 2) {
            float4 p = prow[e >> 1];               // {s0,x0,s1,x1}
            int s0 = __float_as_int(p.x);
            int s1 = __float_as_int(p.z);
            ulonglong2 h0 = h1u[s0 * 16 + hl];
            ulonglong2 h1r = h1u[s1 * 16 + hl];
            u64 d0 = dup2(p.y), d1 = dup2(p.w);
            accL = fma2(d0, h0.x, accL); accH = fma2(d0, h0.y, accH);
            accL = fma2(d1, h1r.x, accL); accH = fma2(d1, h1r.y, accH);
        }
        __syncwarp();
    }

#pragma unroll
    for (int o = 8; o; o >>= 1) {
        den.x += __shfl_xor_sync(0xffffffffu, den.x, o, 16);
        den.y += __shfl_xor_sync(0xffffffffu, den.y, o, 16);
        den.z += __shfl_xor_sync(0xffffffffu, den.z, o, 16);
        den.w += __shfl_xor_sync(0xffffffffu, den.w, o, 16);
    }

    // self loop
    float4 asd = as1v[dn];
    float4 exs;
    exs.x = __expf(lrelu(asd.x + ad4.x));
    exs.y = __expf(lrelu(asd.y + ad4.y));
    exs.z = __expf(lrelu(asd.z + ad4.z));
    exs.w = __expf(lrelu(asd.w + ad4.w));
    den.x += exs.x; den.y += exs.y; den.z += exs.z; den.w += exs.w;

    float exm_self = sel4(exs, myh);
    ulonglong2 hdp = h1u[dn * 16 + hl];
    u64 ds = dup2(exm_self);
    accL = fma2(ds, hdp.x, accL);
    accH = fma2(ds, hdp.y, accH);

    float2 aL = unpack2(accL), aH = unpack2(accH);
    float inv = 1.f / (sel4(den, myh) + 1e-16f);
    float4 bv = ((const float4*)b1)[hl];
    float4 o;
    o.x = aL.x * inv + bv.x;
    o.y = aL.y * inv + bv.y;
    o.z = aH.x * inv + bv.z;
    o.w = aH.y * inv + bv.w;
    o.x = o.x > 0.f ? o.x : expm1f(o.x);
    o.y = o.y > 0.f ? o.y : expm1f(o.y);
    o.z = o.z > 0.f ? o.z : expm1f(o.z);
    o.w = o.w > 0.f ? o.w : expm1f(o.w);

    // ---- fused gemm2: h2[dn][hl] = hact(dn) . W2[:,hl] --------------------
    sh_hact[warp][half][hl] = o;
    __syncwarp();
    float acc2 = 0.f;
#pragma unroll
    for (int kk = 0; kk < 16; kk++) {
        float4 h4 = sh_hact[warp][half][kk];
        acc2 += h4.x * W2sh[(kk * 4 + 0) * CC + hl];
        acc2 += h4.y * W2sh[(kk * 4 + 1) * CC + hl];
        acc2 += h4.z * W2sh[(kk * 4 + 2) * CC + hl];
        acc2 += h4.w * W2sh[(kk * 4 + 3) * CC + hl];
    }
    g_h2[dn * CC + hl] = acc2;

    // ---- fused attn2 ------------------------------------------------------
    float ta = acc2 * asrc2[hl];
    float td = acc2 * adst2[hl];
#pragma unroll
    for (int of = 8; of; of >>= 1) {
        ta += __shfl_xor_sync(0xffffffffu, ta, of, 16);
        td += __shfl_xor_sync(0xffffffffu, td, of, 16);
    }
    if (hl == 0) {
        g_as2[dn] = ta;
        g_ad2[dn] = td;
    }
}

// ---------------- layer-2 softmax + aggregation ------------------------------
__global__ void __launch_bounds__(256) gat_agg2_kernel(const float* __restrict__ b2,
                                                       float* __restrict__ out) {
    __shared__ int   sh_s[8][32];
    __shared__ float sh_ex[8][32];
    int warp = threadIdx.x >> 5, lane = threadIdx.x & 31;
    int half = lane >> 4, hl = lane & 15;
    int dn = (blockIdx.x * 8 + warp) * 2 + half;

    float ad = g_ad2[dn];
    int row = g_rowptr[dn];
    int deg = g_rowptr[dn + 1] - row;
    int degmax = max(deg, __shfl_xor_sync(0xffffffffu, deg, 16));
    float den = 0.f;
    float a0 = 0.f, a1 = 0.f;
    int bs = half * 16;

    for (int base = 0; base < degmax; base += 16) {
        int j = base + hl;
        bool valid = j < deg;
        int idx = row + (valid ? j : 0);
        idx = idx < EE ? idx : EE - 1;
        int s = g_csr[idx];
        float ex = 0.f;
        if (valid) {
            ex = __expf(lrelu(g_as2[s] + ad));
            den += ex;
        }
        sh_s[warp][lane] = s;
        sh_ex[warp][lane] = ex;
        __syncwarp();

        int cnt = deg - base;
        cnt = cnt < 0 ? 0 : (cnt > 16 ? 16 : cnt);
        int jj = 0;
        for (; jj + 2 <= cnt; jj += 2) {
            int s0 = sh_s[warp][bs + jj];
            int s1 = sh_s[warp][bs + jj + 1];
            float x0 = sh_ex[warp][bs + jj];
            float x1 = sh_ex[warp][bs + jj + 1];
            a0 += x0 * g_h2[s0 * 16 + hl];
            a1 += x1 * g_h2[s1 * 16 + hl];
        }
        if (jj < cnt) {
            int s0 = sh_s[warp][bs + jj];
            float x0 = sh_ex[warp][bs + jj];
            a0 += x0 * g_h2[s0 * 16 + hl];
        }
        __syncwarp();
    }
    float acc = a0 + a1;
#pragma unroll
    for (int o = 8; o; o >>= 1) den += __shfl_xor_sync(0xffffffffu, den, o, 16);

    float exs = __expf(lrelu(g_as2[dn] + ad));
    den += exs;
    acc += exs * g_h2[dn * 16 + hl];
    out[dn * 16 + hl] = acc / (den + 1e-16f) + b2[hl];
}

// ---------------- launch ------------------------------------------------------
extern "C" void kernel_launch(void* const* d_in, const int* in_sizes, int n_in,
                              void* d_out, int out_size) {
    const float* x      = (const float*)d_in[0];
    const void*  ei     = d_in[1];
    const float* W1     = (const float*)d_in[2];
    const float* a_src1 = (const float*)d_in[3];
    const float* a_dst1 = (const float*)d_in[4];
    const float* b1     = (const float*)d_in[5];
    const float* W2     = (const float*)d_in[6];
    const float* a_src2 = (const float*)d_in[7];
    const float* a_dst2 = (const float*)d_in[8];
    const float* b2     = (const float*)d_in[9];
    float* out = (float*)d_out;

    (void)in_sizes; (void)n_in; (void)out_size;

    const int nThreads = 256;
    const int nBlocksN = (NN + nThreads - 1) / nThreads;
    const int nBlocksE = (EE + nThreads - 1) / nThreads;

    // Fork a side stream for the CSR build so it overlaps gemm1.
    cudaStream_t s2;
    cudaStreamCreateWithFlags(&s2, cudaStreamNonBlocking);
    cudaEvent_t eFork, eJoin;
    cudaEventCreateWithFlags(&eFork, cudaEventDisableTiming);
    cudaEventCreateWithFlags(&eJoin, cudaEventDisableTiming);

    cudaEventRecord(eFork, 0);
    cudaStreamWaitEvent(s2, eFork, 0);

    // CSR chain on s2
    zero_deg_kernel<<<nBlocksN, nThreads, 0, s2>>>();
    hist_kernel<<<nBlocksE, nThreads, 0, s2>>>(ei);
    scanA_kernel<<<NB2, 1024, 0, s2>>>();
    scanB_kernel<<<1, 32, 0, s2>>>();
    scanC_kernel<<<nBlocksN, nThreads, 0, s2>>>();
    scatter_kernel<<<nBlocksE, nThreads, 0, s2>>>(ei);
    cudaEventRecord(eJoin, s2);

    // gemm1 on main stream, concurrent with CSR build
    gemm1_kernel<<<(NN + 63) / 64, 256>>>(x, W1, a_src1, a_dst1);

    cudaStreamWaitEvent(0, eJoin, 0);

    gat_agg1_fused_kernel<<<(NN + 15) / 16, 256>>>(b1, W2, a_src2, a_dst2);
    gat_agg2_kernel<<<(NN + 15) / 16, 256>>>(b2, out);

    cudaEventDestroy(eFork);
    cudaEventDestroy(eJoin);
    cudaStreamDestroy(s2);
}